// round 6
// baseline (speedup 1.0000x reference)
#include <cuda_runtime.h>
#include <cuda_bf16.h>
#include <cstdint>

// ---------------- problem constants ----------------
#define TOKENS 512
#define OUT_F  8192
#define IN_F   4096

#define BM 128
#define BN 128
#define BK 64
#define NKT (IN_F / BK)   // 64 k-tiles
#define NTHREADS 256

// ---------------- smem layout (dynamic) ----------------
// LUT: 256 x 8B (byte -> 4 bf16 ternary values)
#define OFF_LUT     0
#define OFF_ALPHA   2048
#define OFF_BIAS    2560
#define OFF_TILE    4096
// per buffer: A_hi 128x64 bf16 (16KB) | A_lo (16KB) | B 128x64 bf16 (16KB)
#define TILE_STRIDE 49152
#define SMEM_BYTES  (OFF_TILE + 2 * TILE_STRIDE)   // 102400

// SW128-style XOR swizzle on 128B rows
#define SWZ(o) ((uint32_t)(o) ^ ((((uint32_t)(o)) >> 3) & 0x70))

__device__ __forceinline__ uint32_t smem_u32(const void* p) {
    uint32_t a;
    asm("{ .reg .u64 t; cvta.to.shared.u64 t, %1; cvt.u32.u64 %0, t; }"
        : "=r"(a) : "l"(p));
    return a;
}

#define LDSM4(R, addr) \
    asm volatile("ldmatrix.sync.aligned.m8n8.x4.shared.b16 {%0,%1,%2,%3}, [%4];" \
        : "=r"((R)[0]), "=r"((R)[1]), "=r"((R)[2]), "=r"((R)[3]) : "r"(addr))

#define MMA16816(C, A, b0, b1) \
    asm volatile("mma.sync.aligned.m16n8k16.row.col.f32.bf16.bf16.f32 " \
        "{%0,%1,%2,%3},{%4,%5,%6,%7},{%8,%9},{%0,%1,%2,%3};" \
        : "+f"((C)[0]), "+f"((C)[1]), "+f"((C)[2]), "+f"((C)[3]) \
        : "r"((A)[0]), "r"((A)[1]), "r"((A)[2]), "r"((A)[3]), "r"(b0), "r"(b1))

__device__ __forceinline__ uint32_t code_bf16(int c) {
    // 2 -> +1.0bf16, 0 -> -1.0bf16, 1/3 -> 0
    return c == 2 ? 0x3F80u : (c == 0 ? 0xBF80u : 0u);
}

__global__ void __launch_bounds__(NTHREADS, 2)
ternary_gemm_bf16(const float* __restrict__ x,
                  const int*   __restrict__ wp,
                  const float* __restrict__ alpha,
                  const float* __restrict__ bias,
                  float*       __restrict__ out) {
    extern __shared__ char smem[];
    const uint32_t sb = smem_u32(smem);
    const int tid = threadIdx.x;
    const int wid = tid >> 5;
    const int L   = tid & 31;

    const int n0 = blockIdx.x * BN;   // output-feature tile
    const int m0 = blockIdx.y * BM;   // token tile

    const int wm = (wid & 1) * 64;    // warp m offset (rows)
    const int wn = (wid >> 1) * 32;   // warp n offset (cols)

    // ---------------- prologue: LUT + alpha/bias ----------------
    {
        uint32_t w0 = code_bf16(tid & 3) | (code_bf16((tid >> 2) & 3) << 16);
        uint32_t w1 = code_bf16((tid >> 4) & 3) | (code_bf16((tid >> 6) & 3) << 16);
        *reinterpret_cast<uint2*>(smem + OFF_LUT + tid * 8) = make_uint2(w0, w1);
    }
    if (tid < BN) {
        reinterpret_cast<float*>(smem + OFF_ALPHA)[tid] = alpha[n0 + tid];
        reinterpret_cast<float*>(smem + OFF_BIAS)[tid]  = bias[n0 + tid];
    }
    __syncthreads();

    // ---------------- per-lane ldmatrix address constants ----------------
    // A (and A_lo): [m][k] rows of 128B. x4 matrices: (m0-7,k0-7),(m8-15,k0-7),(m0-7,k8-15),(m8-15,k8-15)
    const int mrow = ((L >> 3) & 1) * 8 + (L & 7);
    const uint32_t a_kx  = (uint32_t)(L >> 4) * 16;     // +8 k -> +16B
    const uint32_t axor  = (uint32_t)(mrow & 7) << 4;
    const uint32_t a_row = (uint32_t)(wm + mrow) * 128;
    // B: [n][k] rows of 128B. x4 matrices: (n0-7,k0-7),(n0-7,k8-15),(n8-15,k0-7),(n8-15,k8-15)
    const int nrow = (L >> 4) * 8 + (L & 7);
    const uint32_t b_kx  = (uint32_t)((L >> 3) & 1) * 16;
    const uint32_t bxor  = (uint32_t)(nrow & 7) << 4;
    const uint32_t b_row = (uint32_t)(wn + nrow) * 128;

    const float4* x4 = reinterpret_cast<const float4*>(x);
    const int4*   w4 = reinterpret_cast<const int4*>(wp);
    const uint2*  lut = reinterpret_cast<const uint2*>(smem + OFF_LUT);

    float acc[4][4][4];
    #pragma unroll
    for (int i = 0; i < 4; i++)
        #pragma unroll
        for (int j = 0; j < 4; j++)
            #pragma unroll
            for (int q = 0; q < 4; q++) acc[i][j][q] = 0.0f;

    float4 xa[8];
    int4   wv[2];

    // ---- load tile 0 ----
    #pragma unroll
    for (int i = 0; i < 8; i++) {
        int u = tid + i * NTHREADS;
        int m = u >> 4, k4 = u & 15;
        xa[i] = x4[(uint32_t)(m0 + m) * (IN_F / 4) + 0 * 16 + k4];
    }
    #pragma unroll
    for (int i = 0; i < 2; i++) {
        int u = tid + i * NTHREADS;
        int n = u >> 2, wq = u & 3;
        wv[i] = w4[(uint32_t)(n0 + n) * (IN_F / 16) + 0 * 4 + wq];
    }
    // ---- store tile 0 into buf 0 ----
    {
        const uint32_t ah = sb + OFF_TILE;
        const uint32_t al = ah + 16384;
        const uint32_t bb = ah + 32768;
        #pragma unroll
        for (int i = 0; i < 8; i++) {
            int u = tid + i * NTHREADS;
            int m = u >> 4, k4 = u & 15;
            float4 v = xa[i];
            __nv_bfloat162 hA = __float22bfloat162_rn(make_float2(v.x, v.y));
            __nv_bfloat162 hB = __float22bfloat162_rn(make_float2(v.z, v.w));
            uint32_t h01 = *reinterpret_cast<uint32_t*>(&hA);
            uint32_t h23 = *reinterpret_cast<uint32_t*>(&hB);
            float l0 = v.x - __uint_as_float(h01 << 16);
            float l1 = v.y - __uint_as_float(h01 & 0xFFFF0000u);
            float l2 = v.z - __uint_as_float(h23 << 16);
            float l3 = v.w - __uint_as_float(h23 & 0xFFFF0000u);
            __nv_bfloat162 lA = __float22bfloat162_rn(make_float2(l0, l1));
            __nv_bfloat162 lB = __float22bfloat162_rn(make_float2(l2, l3));
            uint32_t l01 = *reinterpret_cast<uint32_t*>(&lA);
            uint32_t l23 = *reinterpret_cast<uint32_t*>(&lB);
            uint32_t off = SWZ((uint32_t)m * 128 + (uint32_t)k4 * 8);
            asm volatile("st.shared.v2.b32 [%0], {%1,%2};" :: "r"(ah + off), "r"(h01), "r"(h23));
            asm volatile("st.shared.v2.b32 [%0], {%1,%2};" :: "r"(al + off), "r"(l01), "r"(l23));
        }
        #pragma unroll
        for (int i = 0; i < 2; i++) {
            int u = tid + i * NTHREADS;
            int n = u >> 2, wq = u & 3;
            uint2 e0 = lut[wv[i].x & 255], e1 = lut[wv[i].y & 255];
            uint2 e2 = lut[wv[i].z & 255], e3 = lut[wv[i].w & 255];
            uint32_t o0 = (uint32_t)n * 128 + (uint32_t)wq * 32;
            asm volatile("st.shared.v4.b32 [%0], {%1,%2,%3,%4};"
                :: "r"(bb + SWZ(o0)), "r"(e0.x), "r"(e0.y), "r"(e1.x), "r"(e1.y));
            asm volatile("st.shared.v4.b32 [%0], {%1,%2,%3,%4};"
                :: "r"(bb + SWZ(o0 + 16)), "r"(e2.x), "r"(e2.y), "r"(e3.x), "r"(e3.y));
        }
    }
    __syncthreads();

    // ---------------- main K loop ----------------
    #pragma unroll 1
    for (int kt = 0; kt < NKT; kt++) {
        const int buf = kt & 1;

        // issue next tile's global loads early (overlap with MMA)
        if (kt + 1 < NKT) {
            #pragma unroll
            for (int i = 0; i < 8; i++) {
                int u = tid + i * NTHREADS;
                int m = u >> 4, k4 = u & 15;
                xa[i] = x4[(uint32_t)(m0 + m) * (IN_F / 4) + (kt + 1) * 16 + k4];
            }
            #pragma unroll
            for (int i = 0; i < 2; i++) {
                int u = tid + i * NTHREADS;
                int n = u >> 2, wq = u & 3;
                wv[i] = w4[(uint32_t)(n0 + n) * (IN_F / 16) + (kt + 1) * 4 + wq];
            }
        }

        // ---- MMA on current buffer ----
        {
            const uint32_t base = sb + OFF_TILE + (uint32_t)buf * TILE_STRIDE;
            const uint32_t ahb = base + a_row;
            const uint32_t alb = ahb + 16384;
            const uint32_t bbb = base + 32768 + b_row;
            #pragma unroll
            for (int ks = 0; ks < 4; ks++) {
                const uint32_t koffa = ((uint32_t)(ks * 32) + a_kx) ^ axor;
                const uint32_t koffb = ((uint32_t)(ks * 32) + b_kx) ^ bxor;
                uint32_t bf[8];
                LDSM4(bf,     bbb + koffb);          // n atoms 0,1
                LDSM4(bf + 4, bbb + 2048 + koffb);   // n atoms 2,3
                #pragma unroll
                for (int ma = 0; ma < 4; ma++) {
                    uint32_t af[4];
                    LDSM4(af, ahb + (uint32_t)ma * 2048 + koffa);
                    MMA16816(acc[ma][0], af, bf[0], bf[1]);
                    MMA16816(acc[ma][1], af, bf[2], bf[3]);
                    MMA16816(acc[ma][2], af, bf[4], bf[5]);
                    MMA16816(acc[ma][3], af, bf[6], bf[7]);
                    LDSM4(af, alb + (uint32_t)ma * 2048 + koffa);
                    MMA16816(acc[ma][0], af, bf[0], bf[1]);
                    MMA16816(acc[ma][1], af, bf[2], bf[3]);
                    MMA16816(acc[ma][2], af, bf[4], bf[5]);
                    MMA16816(acc[ma][3], af, bf[6], bf[7]);
                }
            }
        }

        // ---- store next tile into other buffer ----
        if (kt + 1 < NKT) {
            const uint32_t ah = sb + OFF_TILE + (uint32_t)((kt + 1) & 1) * TILE_STRIDE;
            const uint32_t al = ah + 16384;
            const uint32_t bb = ah + 32768;
            #pragma unroll
            for (int i = 0; i < 8; i++) {
                int u = tid + i * NTHREADS;
                int m = u >> 4, k4 = u & 15;
                float4 v = xa[i];
                __nv_bfloat162 hA = __float22bfloat162_rn(make_float2(v.x, v.y));
                __nv_bfloat162 hB = __float22bfloat162_rn(make_float2(v.z, v.w));
                uint32_t h01 = *reinterpret_cast<uint32_t*>(&hA);
                uint32_t h23 = *reinterpret_cast<uint32_t*>(&hB);
                float l0 = v.x - __uint_as_float(h01 << 16);
                float l1 = v.y - __uint_as_float(h01 & 0xFFFF0000u);
                float l2 = v.z - __uint_as_float(h23 << 16);
                float l3 = v.w - __uint_as_float(h23 & 0xFFFF0000u);
                __nv_bfloat162 lA = __float22bfloat162_rn(make_float2(l0, l1));
                __nv_bfloat162 lB = __float22bfloat162_rn(make_float2(l2, l3));
                uint32_t l01 = *reinterpret_cast<uint32_t*>(&lA);
                uint32_t l23 = *reinterpret_cast<uint32_t*>(&lB);
                uint32_t off = SWZ((uint32_t)m * 128 + (uint32_t)k4 * 8);
                asm volatile("st.shared.v2.b32 [%0], {%1,%2};" :: "r"(ah + off), "r"(h01), "r"(h23));
                asm volatile("st.shared.v2.b32 [%0], {%1,%2};" :: "r"(al + off), "r"(l01), "r"(l23));
            }
            #pragma unroll
            for (int i = 0; i < 2; i++) {
                int u = tid + i * NTHREADS;
                int n = u >> 2, wq = u & 3;
                uint2 e0 = lut[wv[i].x & 255], e1 = lut[wv[i].y & 255];
                uint2 e2 = lut[wv[i].z & 255], e3 = lut[wv[i].w & 255];
                uint32_t o0 = (uint32_t)n * 128 + (uint32_t)wq * 32;
                asm volatile("st.shared.v4.b32 [%0], {%1,%2,%3,%4};"
                    :: "r"(bb + SWZ(o0)), "r"(e0.x), "r"(e0.y), "r"(e1.x), "r"(e1.y));
                asm volatile("st.shared.v4.b32 [%0], {%1,%2,%3,%4};"
                    :: "r"(bb + SWZ(o0 + 16)), "r"(e2.x), "r"(e2.y), "r"(e3.x), "r"(e3.y));
            }
        }
        __syncthreads();
    }

    // ---------------- epilogue ----------------
    const float* alpS = reinterpret_cast<const float*>(smem + OFF_ALPHA);
    const float* biaS = reinterpret_cast<const float*>(smem + OFF_BIAS);
    const int r  = L >> 2;
    const int c2 = (L & 3) * 2;

    #pragma unroll
    for (int ma = 0; ma < 4; ma++) {
        #pragma unroll
        for (int na = 0; na < 4; na++) {
            int cl = wn + na * 8 + c2;
            float A0 = alpS[cl], A1 = alpS[cl + 1];
            float B0 = biaS[cl], B1 = biaS[cl + 1];
            int gm = m0 + wm + ma * 16 + r;
            float* p = out + (uint32_t)gm * OUT_F + n0 + cl;
            float2 v0 = make_float2(fmaf(acc[ma][na][0], A0, B0),
                                    fmaf(acc[ma][na][1], A1, B1));
            *reinterpret_cast<float2*>(p) = v0;
            float2 v1 = make_float2(fmaf(acc[ma][na][2], A0, B0),
                                    fmaf(acc[ma][na][3], A1, B1));
            *reinterpret_cast<float2*>(p + 8 * OUT_F) = v1;
        }
    }
}

extern "C" void kernel_launch(void* const* d_in, const int* in_sizes, int n_in,
                              void* d_out, int out_size) {
    const float* x     = (const float*)d_in[0];
    const int*   wp    = (const int*)d_in[1];
    const float* alpha = (const float*)d_in[2];
    const float* bias  = (const float*)d_in[3];
    float*       out   = (float*)d_out;

    static bool configured = false;
    if (!configured) {
        cudaFuncSetAttribute(ternary_gemm_bf16,
                             cudaFuncAttributeMaxDynamicSharedMemorySize, SMEM_BYTES);
        configured = true;
    }

    dim3 grid(OUT_F / BN, TOKENS / BM);   // (64, 4) = 256 CTAs
    ternary_gemm_bf16<<<grid, NTHREADS, SMEM_BYTES>>>(x, wp, alpha, bias, out);
}